// round 7
// baseline (speedup 1.0000x reference)
#include <cuda_runtime.h>
#include <cstdint>

#define BQ 8
#define CQ 32
#define KQ 512
#define IT 4            // i-rows per block in kernel 1

// Uncertain-decision list (worst case B*K*K entries)
__device__ uint32_t g_cnt;
__device__ uint2    g_ent[BQ * KQ * KQ];   // .x = (b<<18)|(i<<9)|j, .y = logit bits

// ---------------------------------------------------------------------------
// Threefry-2x32, key (0, 42); partitionable scheme: bits(idx) = o0 ^ o1 of
// threefry(key, (0, idx)).
// ---------------------------------------------------------------------------
__device__ __forceinline__ uint32_t rotl32(uint32_t x, int r) {
    return (x << r) | (x >> (32 - r));
}
__device__ __forceinline__ void threefry_0_42(uint32_t x0, uint32_t x1,
                                              uint32_t& o0, uint32_t& o1) {
    const uint32_t ks0 = 0u, ks1 = 42u, ks2 = 0u ^ 42u ^ 0x1BD11BDAu;
    x0 += ks0; x1 += ks1;
    x0 += x1; x1 = rotl32(x1, 13); x1 ^= x0;
    x0 += x1; x1 = rotl32(x1, 15); x1 ^= x0;
    x0 += x1; x1 = rotl32(x1, 26); x1 ^= x0;
    x0 += x1; x1 = rotl32(x1, 6);  x1 ^= x0;
    x0 += ks1; x1 += ks2 + 1u;
    x0 += x1; x1 = rotl32(x1, 17); x1 ^= x0;
    x0 += x1; x1 = rotl32(x1, 29); x1 ^= x0;
    x0 += x1; x1 = rotl32(x1, 16); x1 ^= x0;
    x0 += x1; x1 = rotl32(x1, 24); x1 ^= x0;
    x0 += ks2; x1 += ks0 + 2u;
    x0 += x1; x1 = rotl32(x1, 13); x1 ^= x0;
    x0 += x1; x1 = rotl32(x1, 15); x1 ^= x0;
    x0 += x1; x1 = rotl32(x1, 26); x1 ^= x0;
    x0 += x1; x1 = rotl32(x1, 6);  x1 ^= x0;
    x0 += ks0; x1 += ks1 + 3u;
    x0 += x1; x1 = rotl32(x1, 17); x1 ^= x0;
    x0 += x1; x1 = rotl32(x1, 29); x1 ^= x0;
    x0 += x1; x1 = rotl32(x1, 16); x1 ^= x0;
    x0 += x1; x1 = rotl32(x1, 24); x1 ^= x0;
    x0 += ks1; x1 += ks2 + 4u;
    x0 += x1; x1 = rotl32(x1, 13); x1 ^= x0;
    x0 += x1; x1 = rotl32(x1, 15); x1 ^= x0;
    x0 += x1; x1 = rotl32(x1, 26); x1 ^= x0;
    x0 += x1; x1 = rotl32(x1, 6);  x1 ^= x0;
    x0 += ks2; x1 += ks0 + 5u;
    o0 = x0; o1 = x1;
}
__device__ __forceinline__ uint32_t jax_bits_partitionable(uint32_t idx) {
    uint32_t o0, o1;
    threefry_0_42(0u, idx, o0, o1);
    return o0 ^ o1;
}
__device__ __forceinline__ float gumbel_from_bits(uint32_t bits) {
    float f = __uint_as_float((bits >> 9) | 0x3F800000u) - 1.0f;
    float u = fmaxf(__fadd_rn(f, 1e-10f), 1e-10f);
    return -logf(-logf(u));
}

// Add-class ops forced into the FFMA-imm SASS form (rt_SMSP = 1) via scalar
// inline asm; ptxas cannot fold an asm fma back into FADD. Bit-exact:
//   rn(a - b) == fma(b, -1.0, a)    (product -b exact, single rounding)
//   rn(a + b) == fma(a,  1.0, b)    (product a exact, single rounding)
__device__ __forceinline__ float ffma_sub(float a, float b) {
    float d;
    asm("fma.rn.f32 %0, %1, 0fBF800000, %2;" : "=f"(d) : "f"(b), "f"(a));
    return d;
}
__device__ __forceinline__ float ffma_add(float a, float b) {
    float d;
    asm("fma.rn.f32 %0, %1, 0f3F800000, %2;" : "=f"(d) : "f"(a), "f"(b));
    return d;
}

// ---------------------------------------------------------------------------
// Kernel 0: init (replaces memsets; also shifts the ncu capture period so
// launch index 5 = first k_logit half -> we finally profile k_logit).
// ---------------------------------------------------------------------------
__global__ void __launch_bounds__(512)
k_init(float* __restrict__ out) {
    uint32_t idx = blockIdx.x * 512u + threadIdx.x;
    out[idx] = 0.0f;
    if (idx == 0) g_cnt = 0;
}

// ---------------------------------------------------------------------------
// Kernel 1: logits + uncertain-list compaction.
// Launched twice (b0 = 0, 4) with grid (KQ/IT, BQ/2), 512 threads (thread=j).
// ---------------------------------------------------------------------------
__global__ void __launch_bounds__(KQ)
k_logit(const float* __restrict__ amp, const float* __restrict__ ph,
        const float* __restrict__ A,
        const float* __restrict__ wa_p, const float* __restrict__ wp_p,
        int b0) {
    const int b  = b0 + blockIdx.y;
    const int i0 = blockIdx.x * IT;
    const int j  = threadIdx.x;

    __shared__ float    s_ai[CQ][IT];
    __shared__ float    s_pi[CQ][IT];
    __shared__ float    s_max[IT][16];
    __shared__ uint32_t s_cnt;
    __shared__ uint32_t s_base;

    const float wa = wa_p[0];
    const float wp = wp_p[0];
    // wa = wp = 0.5 fast path is bit-exact: rn(0.5*x) exact (pow-2 scale), so
    // f = rn(0.5*ad + 0.5*pd) = 0.5*rn(ad+pd) and rn(f*Ajj) = rn(s*(0.5*Ajj)).
    const bool half = (__float_as_uint(wa) == 0x3F000000u) &&
                      (__float_as_uint(wp) == 0x3F000000u);

    if (threadIdx.x == 0) s_cnt = 0;
    if (threadIdx.x < IT * CQ) {
        int t = threadIdx.x % IT;
        int c = threadIdx.x / IT;
        s_ai[c][t] = amp[(b * CQ + c) * KQ + i0 + t];
        s_pi[c][t] = ph [(b * CQ + c) * KQ + i0 + t];
    }
    __syncthreads();

    const float Ajj = A[j * KQ + j];
    const float Aj2 = __fmul_rn(0.5f, Ajj);   // exact

    float acc[IT];
#pragma unroll
    for (int t = 0; t < IT; t++) acc[t] = 0.0f;

    const float* ap = amp + (size_t)b * CQ * KQ + j;
    const float* pp = ph  + (size_t)b * CQ * KQ + j;

    if (half) {
#pragma unroll 8
        for (int c = 0; c < CQ; c++) {
            float aj = ap[c * KQ];
            float pj = pp[c * KQ];
#pragma unroll
            for (int t = 0; t < IT; t++) {
                float ad = ffma_sub(s_ai[c][t], aj);   // rn(ai - aj), FFMA-imm
                float pd = ffma_sub(s_pi[c][t], pj);   // rn(pi - pj), FFMA-imm
                float s  = ffma_add(ad, pd);           // = 2*f bit-exactly
                float tt = __fmul_rn(s, Aj2);          // = rn(f*Ajj)
                float sq = __fmul_rn(tt, tt);
                acc[t]   = ffma_add(sq, acc[t]);       // FFMA-imm
            }
        }
    } else {
#pragma unroll 8
        for (int c = 0; c < CQ; c++) {
            float aj = ap[c * KQ];
            float pj = pp[c * KQ];
#pragma unroll
            for (int t = 0; t < IT; t++) {
                float ad = ffma_sub(s_ai[c][t], aj);
                float pd = ffma_sub(s_pi[c][t], pj);
                float f  = ffma_add(__fmul_rn(wa, ad), __fmul_rn(wp, pd));
                float tt = __fmul_rn(f, Ajj);
                float sq = __fmul_rn(tt, tt);
                acc[t]   = ffma_add(sq, acc[t]);
            }
        }
    }

    float ed[IT];
#pragma unroll
    for (int t = 0; t < IT; t++) {
        float d = __fadd_rn(acc[t], 1e-10f);
        float e = __fdiv_rn(1.0f, d);
        if (j == i0 + t) e = 0.0f;           // offdiag mask before the max
        ed[t] = e;
        float m = e;
#pragma unroll
        for (int o = 16; o > 0; o >>= 1)
            m = fmaxf(m, __shfl_xor_sync(0xFFFFFFFFu, m, o));
        if ((threadIdx.x & 31) == 0) s_max[t][threadIdx.x >> 5] = m;
    }
    __syncthreads();

    float lg[IT];
    int nunc = 0;
    int tlist[IT];
#pragma unroll
    for (int t = 0; t < IT; t++) {
        float m = s_max[t][0];
#pragma unroll
        for (int w = 1; w < 16; w++) m = fmaxf(m, s_max[t][w]);

        if (j == i0 + t) {
            // diag: p = 0.99 exactly
            float l = logf(__fdiv_rn(0.99f, __fsub_rn(1.0f, 0.99f)));
            lg[t] = l; tlist[nunc++] = t;
        } else if (ed[t] > __fmul_rn(4.5e-5f, m)) {
            // prefilter: e <= 4.5e-5*m provably implies 2l <= -20 (certain 0);
            // candidates still run the exact div+logf+test, so the list is
            // bit-identical to the unfiltered version.
            float p = __fmul_rn(__fdiv_rn(ed[t], m), 0.99f);
            float l = logf(__fdiv_rn(p, __fsub_rn(1.0f, p)));
            if (!(__fadd_rn(l, l) <= -20.0f)) { lg[t] = l; tlist[nunc] = t; nunc++; }
        }
    }

    int rank = 0;
    if (nunc > 0) rank = atomicAdd(&s_cnt, (uint32_t)nunc);
    __syncthreads();
    if (threadIdx.x == 0 && s_cnt > 0) s_base = atomicAdd(&g_cnt, s_cnt);
    __syncthreads();

    for (int q = 0; q < nunc; q++) {
        int t = tlist[q];
        uint2 ent;
        ent.x = ((uint32_t)b << 18) | ((uint32_t)(i0 + t) << 9) | (uint32_t)j;
        ent.y = __float_as_uint(lg[t]);
        g_ent[s_base + rank + q] = ent;
    }
}

// ---------------------------------------------------------------------------
// Kernel 2: process the compacted uncertain list, scatter exact 1/8 adds.
// ---------------------------------------------------------------------------
__global__ void __launch_bounds__(256)
k_sample2(float* __restrict__ out) {
    const uint32_t n = g_cnt;
    const uint32_t stride = gridDim.x * blockDim.x;
    for (uint32_t k = blockIdx.x * blockDim.x + threadIdx.x; k < n; k += stride) {
        uint2 ent = g_ent[k];
        float l = __uint_as_float(ent.y);
        uint32_t flat = ent.x << 1;      // flat index into (B,K,K,2)
        float g0 = gumbel_from_bits(jax_bits_partitionable(flat));
        float g1 = gumbel_from_bits(jax_bits_partitionable(flat + 1u));
        // argmax over {l+g0, -l+g1}; tie -> index 0 -> sample = 1
        if (__fadd_rn(l, g0) >= __fadd_rn(-l, g1))
            atomicAdd(out + (ent.x & 0x3FFFFu), 0.125f);   // exact multiples of 1/8
    }
}

// ---------------------------------------------------------------------------
extern "C" void kernel_launch(void* const* d_in, const int* in_sizes, int n_in,
                              void* d_out, int out_size) {
    const float* amp = (const float*)d_in[0];   // (B, C, K)
    const float* ph  = (const float*)d_in[1];   // (B, C, K)
    const float* A   = (const float*)d_in[2];   // (K, K)
    const float* wa  = (const float*)d_in[3];   // scalar
    const float* wp  = (const float*)d_in[4];   // scalar
    float* out = (float*)d_out;                  // (K, K)

    // Kernel sequence period = 4 -> ncu (-s 5 -c 1) captures k_logit (b0=0).
    k_init<<<KQ * KQ / 512, 512>>>(out);
    dim3 g1(KQ / IT, BQ / 2);
    k_logit<<<g1, KQ>>>(amp, ph, A, wa, wp, 0);
    k_logit<<<g1, KQ>>>(amp, ph, A, wa, wp, 4);
    k_sample2<<<1024, 256>>>(out);
}